// round 1
// baseline (speedup 1.0000x reference)
#include <cuda_runtime.h>
#include <cuda_bf16.h>
#include <math.h>

// ---------------- problem constants ----------------
constexpr int NH   = 16;            // heads
constexpr int HD   = 64;            // head dim
constexpr int DXC  = NH * HD;       // 1024
constexpr int BATCH = 4;
constexpr int SEQ   = 2048;
constexpr int MROWS = BATCH * SEQ;  // 8192

// ---------------- scratch (static device globals; no allocation) ----------------
__device__ float g_Q[BATCH * NH * SEQ * HD];
__device__ float g_K[BATCH * NH * SEQ * HD];
__device__ float g_V[BATCH * NH * SEQ * HD];
__device__ float g_R[BATCH * NH * SEQ * HD];
__device__ float g_gated[MROWS * DXC];

// ---------------- generic GEMM: C = A[M,K] @ W[N,K]^T + bias[N] ----------------
// heads_layout: scatter C[m,n] -> out[((b*NH+h)*SEQ + s)*HD + d]
#define TBM 64
#define TBN 64
#define TBK 16

__global__ void __launch_bounds__(256) gemm_bias_kernel(
    const float* __restrict__ A, const float* __restrict__ W,
    const float* __restrict__ bias, float* __restrict__ C,
    int M, int N, int K, int heads_layout)
{
    __shared__ float As[TBK][TBM + 1];
    __shared__ float Ws[TBK][TBN + 1];

    const int tid = threadIdx.x;
    const int tx = tid & 15;
    const int ty = tid >> 4;
    const int m0 = blockIdx.y * TBM;
    const int n0 = blockIdx.x * TBN;

    const int lr = tid >> 2;         // 0..63 row within tile
    const int lc = (tid & 3) << 2;   // 0,4,8,12 col within k-slab

    float acc[4][4] = {};

    for (int k0 = 0; k0 < K; k0 += TBK) {
        float4 av = *(const float4*)&A[(size_t)(m0 + lr) * K + k0 + lc];
        float4 wv = *(const float4*)&W[(size_t)(n0 + lr) * K + k0 + lc];
        As[lc + 0][lr] = av.x; As[lc + 1][lr] = av.y;
        As[lc + 2][lr] = av.z; As[lc + 3][lr] = av.w;
        Ws[lc + 0][lr] = wv.x; Ws[lc + 1][lr] = wv.y;
        Ws[lc + 2][lr] = wv.z; Ws[lc + 3][lr] = wv.w;
        __syncthreads();

        #pragma unroll
        for (int kk = 0; kk < TBK; kk++) {
            float a[4], b[4];
            #pragma unroll
            for (int i = 0; i < 4; i++) a[i] = As[kk][ty + i * 16];
            #pragma unroll
            for (int j = 0; j < 4; j++) b[j] = Ws[kk][tx + j * 16];
            #pragma unroll
            for (int i = 0; i < 4; i++)
                #pragma unroll
                for (int j = 0; j < 4; j++)
                    acc[i][j] = fmaf(a[i], b[j], acc[i][j]);
        }
        __syncthreads();
    }

    #pragma unroll
    for (int i = 0; i < 4; i++) {
        const int m = m0 + ty + i * 16;
        #pragma unroll
        for (int j = 0; j < 4; j++) {
            const int n = n0 + tx + j * 16;
            const float v = acc[i][j] + bias[n];
            if (heads_layout) {
                const int b = m / SEQ, s = m % SEQ;
                const int h = n / HD,  d = n % HD;
                C[(size_t)((b * NH + h) * SEQ + s) * HD + d] = v;
            } else {
                C[(size_t)m * N + n] = v;
            }
        }
    }
}

// ---------------- flash attention + R-gating ----------------
// grid: (SEQ/64, BATCH*NH), block 256
#define BR 64
#define KC 32

__global__ void __launch_bounds__(256) flash_gate_kernel(
    const float* __restrict__ Qg, const float* __restrict__ Kg,
    const float* __restrict__ Vg, const float* __restrict__ Rg,
    float* __restrict__ gated)
{
    __shared__ float Qs[BR][HD + 1];
    __shared__ float Ks[KC][HD + 1];
    __shared__ float Vs[KC][HD + 1];
    __shared__ float Ss[BR][KC + 1];
    __shared__ float mS[BR], lS[BR], aS[BR];

    const int tid = threadIdx.x;
    const int tx = tid & 15;
    const int ty = tid >> 4;
    const int bh = blockIdx.y;
    const int q0 = blockIdx.x * BR;

    const float* Qb = Qg + (size_t)bh * SEQ * HD;
    const float* Kb = Kg + (size_t)bh * SEQ * HD;
    const float* Vb = Vg + (size_t)bh * SEQ * HD;

    // load Q tile: 64x64 floats = 1024 float4
    for (int t = tid; t < BR * HD / 4; t += 256) {
        const int r = t / (HD / 4);
        const int c = (t % (HD / 4)) * 4;
        float4 v4 = *(const float4*)&Qb[(size_t)(q0 + r) * HD + c];
        Qs[r][c + 0] = v4.x; Qs[r][c + 1] = v4.y;
        Qs[r][c + 2] = v4.z; Qs[r][c + 3] = v4.w;
    }
    if (tid < BR) { mS[tid] = -1e30f; lS[tid] = 0.0f; }

    float o[4][4] = {};
    __syncthreads();

    for (int kt = 0; kt < SEQ / KC; kt++) {
        const int kb = kt * KC;
        // load K,V tiles: 32x64 each
        for (int t = tid; t < KC * HD / 4; t += 256) {
            const int r = t / (HD / 4);
            const int c = (t % (HD / 4)) * 4;
            float4 kv = *(const float4*)&Kb[(size_t)(kb + r) * HD + c];
            Ks[r][c + 0] = kv.x; Ks[r][c + 1] = kv.y;
            Ks[r][c + 2] = kv.z; Ks[r][c + 3] = kv.w;
            float4 vv = *(const float4*)&Vb[(size_t)(kb + r) * HD + c];
            Vs[r][c + 0] = vv.x; Vs[r][c + 1] = vv.y;
            Vs[r][c + 2] = vv.z; Vs[r][c + 3] = vv.w;
        }
        __syncthreads();

        // S = (Q K^T) * 0.125 : rows ty+ii*16 (4), cols tx+jj*16 (2)
        float sacc[4][2] = {};
        #pragma unroll
        for (int d0 = 0; d0 < HD; d0++) {
            float a0 = Qs[ty +  0][d0], a1 = Qs[ty + 16][d0];
            float a2 = Qs[ty + 32][d0], a3 = Qs[ty + 48][d0];
            float b0 = Ks[tx][d0], b1 = Ks[tx + 16][d0];
            sacc[0][0] = fmaf(a0, b0, sacc[0][0]); sacc[0][1] = fmaf(a0, b1, sacc[0][1]);
            sacc[1][0] = fmaf(a1, b0, sacc[1][0]); sacc[1][1] = fmaf(a1, b1, sacc[1][1]);
            sacc[2][0] = fmaf(a2, b0, sacc[2][0]); sacc[2][1] = fmaf(a2, b1, sacc[2][1]);
            sacc[3][0] = fmaf(a3, b0, sacc[3][0]); sacc[3][1] = fmaf(a3, b1, sacc[3][1]);
        }
        #pragma unroll
        for (int i = 0; i < 4; i++)
            #pragma unroll
            for (int j = 0; j < 2; j++)
                Ss[ty + i * 16][tx + j * 16] = sacc[i][j] * 0.125f;
        __syncthreads();

        // online softmax row pass (one thread per row)
        if (tid < BR) {
            const int r = tid;
            const float mold = mS[r];
            float mx = mold;
            #pragma unroll
            for (int j = 0; j < KC; j++) mx = fmaxf(mx, Ss[r][j]);
            const float a = __expf(mold - mx);
            float sum = 0.0f;
            #pragma unroll
            for (int j = 0; j < KC; j++) {
                const float p = __expf(Ss[r][j] - mx);
                Ss[r][j] = p;
                sum += p;
            }
            mS[r] = mx;
            lS[r] = lS[r] * a + sum;
            aS[r] = a;
        }
        __syncthreads();

        // O = O*alpha + P @ V
        float al[4];
        #pragma unroll
        for (int i = 0; i < 4; i++) al[i] = aS[ty + i * 16];
        #pragma unroll
        for (int i = 0; i < 4; i++)
            #pragma unroll
            for (int j = 0; j < 4; j++)
                o[i][j] *= al[i];
        #pragma unroll
        for (int j = 0; j < KC; j++) {
            float p0 = Ss[ty +  0][j], p1 = Ss[ty + 16][j];
            float p2 = Ss[ty + 32][j], p3 = Ss[ty + 48][j];
            float v0 = Vs[j][tx +  0], v1 = Vs[j][tx + 16];
            float v2 = Vs[j][tx + 32], v3 = Vs[j][tx + 48];
            o[0][0] = fmaf(p0, v0, o[0][0]); o[0][1] = fmaf(p0, v1, o[0][1]);
            o[0][2] = fmaf(p0, v2, o[0][2]); o[0][3] = fmaf(p0, v3, o[0][3]);
            o[1][0] = fmaf(p1, v0, o[1][0]); o[1][1] = fmaf(p1, v1, o[1][1]);
            o[1][2] = fmaf(p1, v2, o[1][2]); o[1][3] = fmaf(p1, v3, o[1][3]);
            o[2][0] = fmaf(p2, v0, o[2][0]); o[2][1] = fmaf(p2, v1, o[2][1]);
            o[2][2] = fmaf(p2, v2, o[2][2]); o[2][3] = fmaf(p2, v3, o[2][3]);
            o[3][0] = fmaf(p3, v0, o[3][0]); o[3][1] = fmaf(p3, v1, o[3][1]);
            o[3][2] = fmaf(p3, v2, o[3][2]); o[3][3] = fmaf(p3, v3, o[3][3]);
        }
        __syncthreads();
    }

    // finalize: O /= l, gate with R, scatter to [B,S,DX]
    const int b = bh / NH;
    const int h = bh % NH;
    float linv[4];
    #pragma unroll
    for (int i = 0; i < 4; i++) linv[i] = 1.0f / lS[ty + i * 16];
    #pragma unroll
    for (int i = 0; i < 4; i++) {
        const int s = q0 + ty + i * 16;
        #pragma unroll
        for (int j = 0; j < 4; j++) {
            const int d = tx + j * 16;
            const float r = Rg[((size_t)bh * SEQ + s) * HD + d];
            gated[(size_t)(b * SEQ + s) * DXC + h * HD + d] = o[i][j] * linv[i] * r;
        }
    }
}

// ---------------- launch ----------------
extern "C" void kernel_launch(void* const* d_in, const int* in_sizes, int n_in,
                              void* d_out, int out_size)
{
    const float* value  = (const float*)d_in[0];
    const float* key_   = (const float*)d_in[1];
    const float* query  = (const float*)d_in[2];
    const float* Wq_w   = (const float*)d_in[3];
    const float* Wq_b   = (const float*)d_in[4];
    const float* Wk_w   = (const float*)d_in[5];
    const float* Wk_b   = (const float*)d_in[6];
    const float* Wv_w   = (const float*)d_in[7];
    const float* Wv_b   = (const float*)d_in[8];
    const float* Wr_w   = (const float*)d_in[9];
    const float* Wr_b   = (const float*)d_in[10];
    const float* Wout_w = (const float*)d_in[11];
    const float* Wout_b = (const float*)d_in[12];
    float* out = (float*)d_out;

    float *pQ, *pK, *pV, *pR, *pG;
    cudaGetSymbolAddress((void**)&pQ, g_Q);
    cudaGetSymbolAddress((void**)&pK, g_K);
    cudaGetSymbolAddress((void**)&pV, g_V);
    cudaGetSymbolAddress((void**)&pR, g_R);
    cudaGetSymbolAddress((void**)&pG, g_gated);

    dim3 gGrid(DXC / TBN, MROWS / TBM);   // (16, 128)
    gemm_bias_kernel<<<gGrid, 256>>>(query, Wq_w, Wq_b, pQ, MROWS, DXC, DXC, 1);
    gemm_bias_kernel<<<gGrid, 256>>>(key_,  Wk_w, Wk_b, pK, MROWS, DXC, DXC, 1);
    gemm_bias_kernel<<<gGrid, 256>>>(value, Wv_w, Wv_b, pV, MROWS, DXC, DXC, 1);
    gemm_bias_kernel<<<gGrid, 256>>>(query, Wr_w, Wr_b, pR, MROWS, DXC, DXC, 1);

    dim3 fGrid(SEQ / BR, BATCH * NH);     // (32, 64)
    flash_gate_kernel<<<fGrid, 256>>>(pQ, pK, pV, pR, pG);

    gemm_bias_kernel<<<gGrid, 256>>>(pG, Wout_w, Wout_b, out, MROWS, DXC, DXC, 0);
}

// round 2
// speedup vs baseline: 2.5791x; 2.5791x over previous
#include <cuda_runtime.h>
#include <math.h>
#include <stdint.h>

// ---------------- problem constants ----------------
constexpr int NH    = 16;
constexpr int HD    = 64;
constexpr int DXC   = 1024;
constexpr int BATCH = 4;
constexpr int SEQ   = 2048;
constexpr int MROWS = 8192;

// ---------------- scratch ----------------
__device__ float g_Q[BATCH * NH * SEQ * HD];
__device__ float g_K[BATCH * NH * SEQ * HD];
__device__ float g_V[BATCH * NH * SEQ * HD];
__device__ float g_R[BATCH * NH * SEQ * HD];
__device__ float g_gated[MROWS * DXC];

// ---------------- helpers ----------------
__device__ __forceinline__ uint32_t f2tf(float f) {
    uint32_t u;
    asm("cvt.rna.tf32.f32 %0, %1;" : "=r"(u) : "f"(f));
    return u;
}

// D += A * B  (m16n8k8 tf32)
__device__ __forceinline__ void mma8(float* d, const uint32_t* a, const uint32_t* b) {
    asm volatile(
        "mma.sync.aligned.m16n8k8.row.col.f32.tf32.tf32.f32 "
        "{%0,%1,%2,%3},{%4,%5,%6,%7},{%8,%9},{%0,%1,%2,%3};\n"
        : "+f"(d[0]), "+f"(d[1]), "+f"(d[2]), "+f"(d[3])
        : "r"(a[0]), "r"(a[1]), "r"(a[2]), "r"(a[3]), "r"(b[0]), "r"(b[1]));
}

// =====================================================================
// GEMM (single tf32): C = A[M,1024] @ W[1024,1024]^T + bias
// BM=BN=128, BK=32, 256 threads (8 warps as 4m x 2n, each 32x64)
// =====================================================================
__global__ void __launch_bounds__(256) gemm_tf32_s(
    const float* __restrict__ A, const float* __restrict__ W,
    const float* __restrict__ bias, float* __restrict__ C, int heads_layout)
{
    __shared__ uint32_t Asm[128][36];
    __shared__ uint32_t Bsm[128][36];

    const int tid = threadIdx.x, lane = tid & 31, wid = tid >> 5;
    const int g = lane >> 2, q = lane & 3;
    const int wm = (wid & 3) * 32, wn = (wid >> 2) * 64;
    const int m0 = blockIdx.y * 128, n0 = blockIdx.x * 128;

    float acc[2][8][4] = {};

    const int lrow = tid >> 3;        // 0..31
    const int lcol = (tid & 7) * 4;   // 0..28

    for (int k0 = 0; k0 < 1024; k0 += 32) {
        #pragma unroll
        for (int h = 0; h < 4; h++) {
            const int r = h * 32 + lrow;
            float4 av = *(const float4*)&A[(size_t)(m0 + r) * 1024 + k0 + lcol];
            Asm[r][lcol + 0] = f2tf(av.x); Asm[r][lcol + 1] = f2tf(av.y);
            Asm[r][lcol + 2] = f2tf(av.z); Asm[r][lcol + 3] = f2tf(av.w);
            float4 wv = *(const float4*)&W[(size_t)(n0 + r) * 1024 + k0 + lcol];
            Bsm[r][lcol + 0] = f2tf(wv.x); Bsm[r][lcol + 1] = f2tf(wv.y);
            Bsm[r][lcol + 2] = f2tf(wv.z); Bsm[r][lcol + 3] = f2tf(wv.w);
        }
        __syncthreads();

        #pragma unroll
        for (int kk = 0; kk < 32; kk += 8) {
            uint32_t af[2][4], bf[8][2];
            #pragma unroll
            for (int i = 0; i < 2; i++) {
                const int mb = wm + i * 16;
                af[i][0] = Asm[mb + g][kk + q];
                af[i][1] = Asm[mb + 8 + g][kk + q];
                af[i][2] = Asm[mb + g][kk + 4 + q];
                af[i][3] = Asm[mb + 8 + g][kk + 4 + q];
            }
            #pragma unroll
            for (int j = 0; j < 8; j++) {
                const int nb = wn + j * 8 + g;
                bf[j][0] = Bsm[nb][kk + q];
                bf[j][1] = Bsm[nb][kk + 4 + q];
            }
            #pragma unroll
            for (int i = 0; i < 2; i++)
                #pragma unroll
                for (int j = 0; j < 8; j++)
                    mma8(acc[i][j], af[i], bf[j]);
        }
        __syncthreads();
    }

    #pragma unroll
    for (int i = 0; i < 2; i++) {
        #pragma unroll
        for (int j = 0; j < 8; j++) {
            const int col = n0 + wn + j * 8 + 2 * q;
            const float b0 = bias[col], b1 = bias[col + 1];
            #pragma unroll
            for (int rh = 0; rh < 2; rh++) {
                const int row = m0 + wm + i * 16 + g + rh * 8;
                float v0 = acc[i][j][rh * 2 + 0] + b0;
                float v1 = acc[i][j][rh * 2 + 1] + b1;
                if (heads_layout) {
                    const int b = row >> 11, s = row & 2047;
                    const int h = col >> 6, d = col & 63;
                    *(float2*)&C[(size_t)((b * NH + h) * SEQ + s) * HD + d] = make_float2(v0, v1);
                } else {
                    *(float2*)&C[(size_t)row * 1024 + col] = make_float2(v0, v1);
                }
            }
        }
    }
}

// =====================================================================
// GEMM (split tf32, 3-mma hi/lo): near-fp32 accuracy
// BM=BN=128, BK=16, 256 threads
// =====================================================================
__global__ void __launch_bounds__(256) gemm_tf32_d(
    const float* __restrict__ A, const float* __restrict__ W,
    const float* __restrict__ bias, float* __restrict__ C, int heads_layout)
{
    __shared__ uint32_t Ahi[128][20];
    __shared__ uint32_t Alo[128][20];
    __shared__ uint32_t Bhi[128][20];
    __shared__ uint32_t Blo[128][20];

    const int tid = threadIdx.x, lane = tid & 31, wid = tid >> 5;
    const int g = lane >> 2, q = lane & 3;
    const int wm = (wid & 3) * 32, wn = (wid >> 2) * 64;
    const int m0 = blockIdx.y * 128, n0 = blockIdx.x * 128;

    float acc[2][8][4] = {};

    const int lrow = tid >> 2;        // 0..63
    const int lcol = (tid & 3) * 4;   // 0..12

    for (int k0 = 0; k0 < 1024; k0 += 16) {
        #pragma unroll
        for (int h = 0; h < 2; h++) {
            const int r = h * 64 + lrow;
            float4 av = *(const float4*)&A[(size_t)(m0 + r) * 1024 + k0 + lcol];
            uint32_t a0 = f2tf(av.x), a1 = f2tf(av.y), a2 = f2tf(av.z), a3 = f2tf(av.w);
            *(uint4*)&Ahi[r][lcol] = make_uint4(a0, a1, a2, a3);
            *(uint4*)&Alo[r][lcol] = make_uint4(
                f2tf(av.x - __uint_as_float(a0)), f2tf(av.y - __uint_as_float(a1)),
                f2tf(av.z - __uint_as_float(a2)), f2tf(av.w - __uint_as_float(a3)));
            float4 wv = *(const float4*)&W[(size_t)(n0 + r) * 1024 + k0 + lcol];
            uint32_t b0 = f2tf(wv.x), b1 = f2tf(wv.y), b2 = f2tf(wv.z), b3 = f2tf(wv.w);
            *(uint4*)&Bhi[r][lcol] = make_uint4(b0, b1, b2, b3);
            *(uint4*)&Blo[r][lcol] = make_uint4(
                f2tf(wv.x - __uint_as_float(b0)), f2tf(wv.y - __uint_as_float(b1)),
                f2tf(wv.z - __uint_as_float(b2)), f2tf(wv.w - __uint_as_float(b3)));
        }
        __syncthreads();

        #pragma unroll
        for (int kk = 0; kk < 16; kk += 8) {
            uint32_t ah[2][4], al[2][4], bh[8][2], bl[8][2];
            #pragma unroll
            for (int i = 0; i < 2; i++) {
                const int mb = wm + i * 16;
                ah[i][0] = Ahi[mb + g][kk + q];     al[i][0] = Alo[mb + g][kk + q];
                ah[i][1] = Ahi[mb + 8 + g][kk + q]; al[i][1] = Alo[mb + 8 + g][kk + q];
                ah[i][2] = Ahi[mb + g][kk + 4 + q]; al[i][2] = Alo[mb + g][kk + 4 + q];
                ah[i][3] = Ahi[mb + 8 + g][kk + 4 + q]; al[i][3] = Alo[mb + 8 + g][kk + 4 + q];
            }
            #pragma unroll
            for (int j = 0; j < 8; j++) {
                const int nb = wn + j * 8 + g;
                bh[j][0] = Bhi[nb][kk + q];     bh[j][1] = Bhi[nb][kk + 4 + q];
                bl[j][0] = Blo[nb][kk + q];     bl[j][1] = Blo[nb][kk + 4 + q];
            }
            #pragma unroll
            for (int i = 0; i < 2; i++)
                #pragma unroll
                for (int j = 0; j < 8; j++) {
                    mma8(acc[i][j], al[i], bh[j]);
                    mma8(acc[i][j], ah[i], bl[j]);
                    mma8(acc[i][j], ah[i], bh[j]);
                }
        }
        __syncthreads();
    }

    #pragma unroll
    for (int i = 0; i < 2; i++) {
        #pragma unroll
        for (int j = 0; j < 8; j++) {
            const int col = n0 + wn + j * 8 + 2 * q;
            const float b0 = bias[col], b1 = bias[col + 1];
            #pragma unroll
            for (int rh = 0; rh < 2; rh++) {
                const int row = m0 + wm + i * 16 + g + rh * 8;
                float v0 = acc[i][j][rh * 2 + 0] + b0;
                float v1 = acc[i][j][rh * 2 + 1] + b1;
                if (heads_layout) {
                    const int b = row >> 11, s = row & 2047;
                    const int h = col >> 6, d = col & 63;
                    *(float2*)&C[(size_t)((b * NH + h) * SEQ + s) * HD + d] = make_float2(v0, v1);
                } else {
                    *(float2*)&C[(size_t)row * 1024 + col] = make_float2(v0, v1);
                }
            }
        }
    }
}

// =====================================================================
// Flash attention (tf32 mma) + R-gating
// BR=128 (8 warps x 16 rows), KC=32; V split hi/lo for accuracy.
// grid (SEQ/128, B*NH), 256 threads
// =====================================================================
#define AKC 32

__global__ void __launch_bounds__(256) attn_tf32(
    const float* __restrict__ Qg, const float* __restrict__ Kg,
    const float* __restrict__ Vg, const float* __restrict__ Rg,
    float* __restrict__ gated)
{
    __shared__ uint32_t Ksm[AKC][68];
    __shared__ uint32_t Vhi[AKC][72];
    __shared__ uint32_t Vlo[AKC][72];
    __shared__ uint32_t Ps[128][36];

    const int tid = threadIdx.x, lane = tid & 31, wid = tid >> 5;
    const int g = lane >> 2, q = lane & 3;
    const int bh = blockIdx.y;
    const int q0 = blockIdx.x * 128;
    const int rbase = wid * 16;

    const float* Qb = Qg + (size_t)bh * SEQ * HD;
    const float* Kb = Kg + (size_t)bh * SEQ * HD;
    const float* Vb = Vg + (size_t)bh * SEQ * HD;

    // Q fragments (held in registers for the whole kernel)
    uint32_t qf[8][4];
    {
        const int r0 = q0 + rbase + g;
        #pragma unroll
        for (int t = 0; t < 8; t++) {
            qf[t][0] = f2tf(Qb[(size_t)r0 * HD + t * 8 + q]);
            qf[t][1] = f2tf(Qb[(size_t)(r0 + 8) * HD + t * 8 + q]);
            qf[t][2] = f2tf(Qb[(size_t)r0 * HD + t * 8 + 4 + q]);
            qf[t][3] = f2tf(Qb[(size_t)(r0 + 8) * HD + t * 8 + 4 + q]);
        }
    }

    float o[8][4] = {};
    float mprev0 = -1e30f, mprev1 = -1e30f;
    float lp0 = 0.f, lp1 = 0.f;

    for (int kt = 0; kt < SEQ / AKC; kt++) {
        const int kb = kt * AKC;
        // ---- load K, V(hi/lo) tiles ----
        #pragma unroll
        for (int h = 0; h < 2; h++) {
            const int idx = tid + h * 256;
            const int r = idx >> 4;
            const int c = (idx & 15) * 4;
            float4 kv = *(const float4*)&Kb[(size_t)(kb + r) * HD + c];
            Ksm[r][c + 0] = f2tf(kv.x); Ksm[r][c + 1] = f2tf(kv.y);
            Ksm[r][c + 2] = f2tf(kv.z); Ksm[r][c + 3] = f2tf(kv.w);
            float4 vv = *(const float4*)&Vb[(size_t)(kb + r) * HD + c];
            uint32_t h0 = f2tf(vv.x), h1 = f2tf(vv.y), h2 = f2tf(vv.z), h3 = f2tf(vv.w);
            *(uint4*)&Vhi[r][c] = make_uint4(h0, h1, h2, h3);
            *(uint4*)&Vlo[r][c] = make_uint4(
                f2tf(vv.x - __uint_as_float(h0)), f2tf(vv.y - __uint_as_float(h1)),
                f2tf(vv.z - __uint_as_float(h2)), f2tf(vv.w - __uint_as_float(h3)));
        }
        __syncthreads();

        // ---- S = Q K^T ----
        float s[4][4] = {};
        #pragma unroll
        for (int t = 0; t < 8; t++) {
            #pragma unroll
            for (int j = 0; j < 4; j++) {
                uint32_t bf[2];
                bf[0] = Ksm[j * 8 + g][t * 8 + q];
                bf[1] = Ksm[j * 8 + g][t * 8 + 4 + q];
                mma8(s[j], qf[t], bf);
            }
        }
        #pragma unroll
        for (int j = 0; j < 4; j++)
            #pragma unroll
            for (int e = 0; e < 4; e++) s[j][e] *= 0.125f;

        // ---- online softmax ----
        float ml0 = s[0][0], ml1 = s[0][2];
        #pragma unroll
        for (int j = 0; j < 4; j++) {
            ml0 = fmaxf(ml0, fmaxf(s[j][0], s[j][1]));
            ml1 = fmaxf(ml1, fmaxf(s[j][2], s[j][3]));
        }
        ml0 = fmaxf(ml0, __shfl_xor_sync(0xffffffffu, ml0, 1));
        ml0 = fmaxf(ml0, __shfl_xor_sync(0xffffffffu, ml0, 2));
        ml1 = fmaxf(ml1, __shfl_xor_sync(0xffffffffu, ml1, 1));
        ml1 = fmaxf(ml1, __shfl_xor_sync(0xffffffffu, ml1, 2));
        const float mn0 = fmaxf(mprev0, ml0);
        const float mn1 = fmaxf(mprev1, ml1);
        const float al0 = __expf(mprev0 - mn0);
        const float al1 = __expf(mprev1 - mn1);
        float sum0 = 0.f, sum1 = 0.f;
        #pragma unroll
        for (int j = 0; j < 4; j++) {
            s[j][0] = __expf(s[j][0] - mn0); sum0 += s[j][0];
            s[j][1] = __expf(s[j][1] - mn0); sum0 += s[j][1];
            s[j][2] = __expf(s[j][2] - mn1); sum1 += s[j][2];
            s[j][3] = __expf(s[j][3] - mn1); sum1 += s[j][3];
        }
        lp0 = lp0 * al0 + sum0;
        lp1 = lp1 * al1 + sum1;
        mprev0 = mn0; mprev1 = mn1;
        #pragma unroll
        for (int j = 0; j < 8; j++) {
            o[j][0] *= al0; o[j][1] *= al0;
            o[j][2] *= al1; o[j][3] *= al1;
        }

        // ---- P -> smem (layout conversion C-frag -> A-frag) ----
        #pragma unroll
        for (int j = 0; j < 4; j++) {
            *(uint2*)&Ps[rbase + g][j * 8 + 2 * q]     = make_uint2(f2tf(s[j][0]), f2tf(s[j][1]));
            *(uint2*)&Ps[rbase + 8 + g][j * 8 + 2 * q] = make_uint2(f2tf(s[j][2]), f2tf(s[j][3]));
        }
        __syncwarp();

        // ---- O += P V (V = Vhi + Vlo) ----
        #pragma unroll
        for (int t = 0; t < 4; t++) {
            uint32_t af[4];
            af[0] = Ps[rbase + g][t * 8 + q];
            af[1] = Ps[rbase + 8 + g][t * 8 + q];
            af[2] = Ps[rbase + g][t * 8 + 4 + q];
            af[3] = Ps[rbase + 8 + g][t * 8 + 4 + q];
            #pragma unroll
            for (int j = 0; j < 8; j++) {
                uint32_t bv[2];
                bv[0] = Vhi[t * 8 + q][j * 8 + g];
                bv[1] = Vhi[t * 8 + 4 + q][j * 8 + g];
                mma8(o[j], af, bv);
                bv[0] = Vlo[t * 8 + q][j * 8 + g];
                bv[1] = Vlo[t * 8 + 4 + q][j * 8 + g];
                mma8(o[j], af, bv);
            }
        }
        __syncthreads();
    }

    // ---- finalize: normalize, gate with R, scatter to [B,S,DX] ----
    lp0 += __shfl_xor_sync(0xffffffffu, lp0, 1);
    lp0 += __shfl_xor_sync(0xffffffffu, lp0, 2);
    lp1 += __shfl_xor_sync(0xffffffffu, lp1, 1);
    lp1 += __shfl_xor_sync(0xffffffffu, lp1, 2);
    const float inv0 = 1.0f / lp0, inv1 = 1.0f / lp1;

    const int b = bh >> 4, hh = bh & 15;
    const int s0 = q0 + rbase + g;
    const float* Rb = Rg + (size_t)bh * SEQ * HD;
    #pragma unroll
    for (int j = 0; j < 8; j++) {
        const int d = j * 8 + 2 * q;
        float2 r0v = *(const float2*)&Rb[(size_t)s0 * HD + d];
        float2 r1v = *(const float2*)&Rb[(size_t)(s0 + 8) * HD + d];
        *(float2*)&gated[(size_t)(b * SEQ + s0) * DXC + hh * HD + d] =
            make_float2(o[j][0] * inv0 * r0v.x, o[j][1] * inv0 * r0v.y);
        *(float2*)&gated[(size_t)(b * SEQ + s0 + 8) * DXC + hh * HD + d] =
            make_float2(o[j][2] * inv1 * r1v.x, o[j][3] * inv1 * r1v.y);
    }
}

// ---------------- launch ----------------
extern "C" void kernel_launch(void* const* d_in, const int* in_sizes, int n_in,
                              void* d_out, int out_size)
{
    const float* value  = (const float*)d_in[0];
    const float* key_   = (const float*)d_in[1];
    const float* query  = (const float*)d_in[2];
    const float* Wq_w   = (const float*)d_in[3];
    const float* Wq_b   = (const float*)d_in[4];
    const float* Wk_w   = (const float*)d_in[5];
    const float* Wk_b   = (const float*)d_in[6];
    const float* Wv_w   = (const float*)d_in[7];
    const float* Wv_b   = (const float*)d_in[8];
    const float* Wr_w   = (const float*)d_in[9];
    const float* Wr_b   = (const float*)d_in[10];
    const float* Wout_w = (const float*)d_in[11];
    const float* Wout_b = (const float*)d_in[12];
    float* out = (float*)d_out;

    float *pQ, *pK, *pV, *pR, *pG;
    cudaGetSymbolAddress((void**)&pQ, g_Q);
    cudaGetSymbolAddress((void**)&pK, g_K);
    cudaGetSymbolAddress((void**)&pV, g_V);
    cudaGetSymbolAddress((void**)&pR, g_R);
    cudaGetSymbolAddress((void**)&pG, g_gated);

    dim3 gGrid(DXC / 128, MROWS / 128);   // (8, 64)
    gemm_tf32_s<<<gGrid, 256>>>(query, Wq_w, Wq_b, pQ, 1);
    gemm_tf32_s<<<gGrid, 256>>>(key_,  Wk_w, Wk_b, pK, 1);
    gemm_tf32_d<<<gGrid, 256>>>(value, Wv_w, Wv_b, pV, 1);
    gemm_tf32_d<<<gGrid, 256>>>(query, Wr_w, Wr_b, pR, 1);

    dim3 aGrid(SEQ / 128, BATCH * NH);    // (16, 64)
    attn_tf32<<<aGrid, 256>>>(pQ, pK, pV, pR, pG);

    gemm_tf32_d<<<gGrid, 256>>>(pG, Wout_w, Wout_b, out, 0);
}

// round 3
// speedup vs baseline: 4.8548x; 1.8824x over previous
#include <cuda_runtime.h>
#include <math.h>
#include <stdint.h>

// ---------------- problem constants ----------------
constexpr int NH    = 16;
constexpr int HD    = 64;
constexpr int DXC   = 1024;
constexpr int BATCH = 4;
constexpr int SEQ   = 2048;
constexpr int MROWS = 8192;

// ---------------- scratch ----------------
__device__ float g_Q[BATCH * NH * SEQ * HD];     // tf32-rounded
__device__ float g_K[BATCH * NH * SEQ * HD];     // tf32-rounded
__device__ float g_V[BATCH * NH * SEQ * HD];     // tf32-rounded
__device__ float g_R[BATCH * NH * SEQ * HD];     // full fp32
__device__ float g_gated[MROWS * DXC];           // tf32-rounded
// tf32-rounded copies of raw inputs / weights
__device__ float g_xq[MROWS * DXC];
__device__ float g_xk[MROWS * DXC];
__device__ float g_xv[MROWS * DXC];
__device__ float g_wq[DXC * DXC];
__device__ float g_wk[DXC * DXC];
__device__ float g_wv[DXC * DXC];
__device__ float g_wr[DXC * DXC];
__device__ float g_wo[DXC * DXC];

// ---------------- helpers ----------------
__device__ __forceinline__ uint32_t f2tf(float f) {
    uint32_t u;
    asm("cvt.rna.tf32.f32 %0, %1;" : "=r"(u) : "f"(f));
    return u;
}
__device__ __forceinline__ float rnd_tf(float f) { return __uint_as_float(f2tf(f)); }

__device__ __forceinline__ void mma8(float* d, const uint32_t* a, const uint32_t* b) {
    asm volatile(
        "mma.sync.aligned.m16n8k8.row.col.f32.tf32.tf32.f32 "
        "{%0,%1,%2,%3},{%4,%5,%6,%7},{%8,%9},{%0,%1,%2,%3};\n"
        : "+f"(d[0]), "+f"(d[1]), "+f"(d[2]), "+f"(d[3])
        : "r"(a[0]), "r"(a[1]), "r"(a[2]), "r"(a[3]), "r"(b[0]), "r"(b[1]));
}

__device__ __forceinline__ void cpa16(void* sdst, const void* gsrc) {
    uint32_t s = (uint32_t)__cvta_generic_to_shared(sdst);
    asm volatile("cp.async.cg.shared.global [%0], [%1], 16;\n" :: "r"(s), "l"(gsrc));
}
__device__ __forceinline__ void cpa_commit() {
    asm volatile("cp.async.commit_group;\n" ::: "memory");
}
template <int N>
__device__ __forceinline__ void cpa_wait() {
    asm volatile("cp.async.wait_group %0;\n" :: "n"(N) : "memory");
}

// ---------------- elementwise tf32 rounding ----------------
__global__ void __launch_bounds__(256) round_tf32_kernel(
    const float* __restrict__ in, float* __restrict__ out, int n4)
{
    int i = blockIdx.x * blockDim.x + threadIdx.x;
    if (i < n4) {
        float4 v = ((const float4*)in)[i];
        v.x = rnd_tf(v.x); v.y = rnd_tf(v.y);
        v.z = rnd_tf(v.z); v.w = rnd_tf(v.w);
        ((float4*)out)[i] = v;
    }
}

// =====================================================================
// Pipelined tf32 GEMM: C = A[8192,1024] @ W[1024,1024]^T + bias
// inputs assumed pre-rounded to tf32. BM=BN=128, BK=32, 256 threads.
// cp.async double-buffered smem; pure LDS+HMMA mainloop.
// heads_layout: scatter to [B,H,S,D]; round_out: tf32-round the result.
// =====================================================================
__global__ void __launch_bounds__(256) gemm_tc(
    const float* __restrict__ A, const float* __restrict__ W,
    const float* __restrict__ bias, float* __restrict__ C,
    int heads_layout, int round_out)
{
    __shared__ __align__(16) float As[2][128][36];
    __shared__ __align__(16) float Bs[2][128][36];

    const int tid = threadIdx.x, lane = tid & 31, wid = tid >> 5;
    const int g = lane >> 2, q = lane & 3;
    const int wm = (wid & 3) * 32, wn = (wid >> 2) * 64;
    const int m0 = blockIdx.y * 128, n0 = blockIdx.x * 128;

    const int lrow = tid >> 3;        // 0..31
    const int lcol = (tid & 7) * 4;   // 0..28

    float acc[2][8][4] = {};

    auto issue = [&](int st, int k0) {
        #pragma unroll
        for (int h = 0; h < 4; h++) {
            const int r = h * 32 + lrow;
            cpa16(&As[st][r][lcol], &A[(size_t)(m0 + r) * 1024 + k0 + lcol]);
            cpa16(&Bs[st][r][lcol], &W[(size_t)(n0 + r) * 1024 + k0 + lcol]);
        }
    };

    issue(0, 0);
    cpa_commit();

    constexpr int KT = 1024 / 32;
    for (int kt = 0; kt < KT; kt++) {
        const int st = kt & 1;
        if (kt + 1 < KT) {
            issue(st ^ 1, (kt + 1) * 32);
            cpa_commit();
            cpa_wait<1>();
        } else {
            cpa_wait<0>();
        }
        __syncthreads();

        #pragma unroll
        for (int kk = 0; kk < 32; kk += 8) {
            uint32_t af[2][4], bf[8][2];
            #pragma unroll
            for (int i = 0; i < 2; i++) {
                const int mb = wm + i * 16;
                af[i][0] = __float_as_uint(As[st][mb + g][kk + q]);
                af[i][1] = __float_as_uint(As[st][mb + 8 + g][kk + q]);
                af[i][2] = __float_as_uint(As[st][mb + g][kk + 4 + q]);
                af[i][3] = __float_as_uint(As[st][mb + 8 + g][kk + 4 + q]);
            }
            #pragma unroll
            for (int j = 0; j < 8; j++) {
                const int nb = wn + j * 8 + g;
                bf[j][0] = __float_as_uint(Bs[st][nb][kk + q]);
                bf[j][1] = __float_as_uint(Bs[st][nb][kk + 4 + q]);
            }
            #pragma unroll
            for (int i = 0; i < 2; i++)
                #pragma unroll
                for (int j = 0; j < 8; j++)
                    mma8(acc[i][j], af[i], bf[j]);
        }
        __syncthreads();
    }

    #pragma unroll
    for (int i = 0; i < 2; i++) {
        #pragma unroll
        for (int j = 0; j < 8; j++) {
            const int col = n0 + wn + j * 8 + 2 * q;
            const float b0 = bias[col], b1 = bias[col + 1];
            #pragma unroll
            for (int rh = 0; rh < 2; rh++) {
                const int row = m0 + wm + i * 16 + g + rh * 8;
                float v0 = acc[i][j][rh * 2 + 0] + b0;
                float v1 = acc[i][j][rh * 2 + 1] + b1;
                if (round_out) { v0 = rnd_tf(v0); v1 = rnd_tf(v1); }
                if (heads_layout) {
                    const int b = row >> 11, s = row & 2047;
                    const int h = col >> 6, d = col & 63;
                    *(float2*)&C[(size_t)((b * NH + h) * SEQ + s) * HD + d] = make_float2(v0, v1);
                } else {
                    *(float2*)&C[(size_t)row * 1024 + col] = make_float2(v0, v1);
                }
            }
        }
    }
}

// =====================================================================
// Flash attention (tf32 mma) + R-gating, cp.async double-buffered K/V
// BR=128 (8 warps x 16 rows), KC=32. Q,K,V pre-rounded to tf32.
// grid (SEQ/128, B*NH), 256 threads
// =====================================================================
#define AKC 32

__global__ void __launch_bounds__(256) attn_tf32(
    const float* __restrict__ Qg, const float* __restrict__ Kg,
    const float* __restrict__ Vg, const float* __restrict__ Rg,
    float* __restrict__ gated)
{
    __shared__ __align__(16) float Ks[2][AKC][68];
    __shared__ __align__(16) float Vs[2][AKC][72];
    __shared__ __align__(16) uint32_t Ps[128][36];

    const int tid = threadIdx.x, lane = tid & 31, wid = tid >> 5;
    const int g = lane >> 2, q = lane & 3;
    const int bh = blockIdx.y;
    const int q0 = blockIdx.x * 128;
    const int rbase = wid * 16;

    const float* Qb = Qg + (size_t)bh * SEQ * HD;
    const float* Kb = Kg + (size_t)bh * SEQ * HD;
    const float* Vb = Vg + (size_t)bh * SEQ * HD;

    // Q fragments in registers (pre-rounded tf32 bits)
    uint32_t qf[8][4];
    {
        const int r0 = q0 + rbase + g;
        #pragma unroll
        for (int t = 0; t < 8; t++) {
            qf[t][0] = __float_as_uint(Qb[(size_t)r0 * HD + t * 8 + q]);
            qf[t][1] = __float_as_uint(Qb[(size_t)(r0 + 8) * HD + t * 8 + q]);
            qf[t][2] = __float_as_uint(Qb[(size_t)r0 * HD + t * 8 + 4 + q]);
            qf[t][3] = __float_as_uint(Qb[(size_t)(r0 + 8) * HD + t * 8 + 4 + q]);
        }
    }

    const int lr = tid >> 4;          // 0..15
    const int lc = (tid & 15) * 4;    // 0..60
    auto issue = [&](int st, int kb) {
        #pragma unroll
        for (int h = 0; h < 2; h++) {
            const int r = h * 16 + lr;
            cpa16(&Ks[st][r][lc], &Kb[(size_t)(kb + r) * HD + lc]);
            cpa16(&Vs[st][r][lc], &Vb[(size_t)(kb + r) * HD + lc]);
        }
    };

    float o[8][4] = {};
    float mprev0 = -1e30f, mprev1 = -1e30f;
    float lp0 = 0.f, lp1 = 0.f;

    issue(0, 0);
    cpa_commit();

    constexpr int NT = SEQ / AKC;
    for (int kt = 0; kt < NT; kt++) {
        const int st = kt & 1;
        if (kt + 1 < NT) {
            issue(st ^ 1, (kt + 1) * AKC);
            cpa_commit();
            cpa_wait<1>();
        } else {
            cpa_wait<0>();
        }
        __syncthreads();

        // ---- S = Q K^T ----
        float s[4][4] = {};
        #pragma unroll
        for (int t = 0; t < 8; t++) {
            #pragma unroll
            for (int j = 0; j < 4; j++) {
                uint32_t bf[2];
                bf[0] = __float_as_uint(Ks[st][j * 8 + g][t * 8 + q]);
                bf[1] = __float_as_uint(Ks[st][j * 8 + g][t * 8 + 4 + q]);
                mma8(s[j], qf[t], bf);
            }
        }
        #pragma unroll
        for (int j = 0; j < 4; j++)
            #pragma unroll
            for (int e = 0; e < 4; e++) s[j][e] *= 0.125f;

        // ---- online softmax ----
        float ml0 = s[0][0], ml1 = s[0][2];
        #pragma unroll
        for (int j = 0; j < 4; j++) {
            ml0 = fmaxf(ml0, fmaxf(s[j][0], s[j][1]));
            ml1 = fmaxf(ml1, fmaxf(s[j][2], s[j][3]));
        }
        ml0 = fmaxf(ml0, __shfl_xor_sync(0xffffffffu, ml0, 1));
        ml0 = fmaxf(ml0, __shfl_xor_sync(0xffffffffu, ml0, 2));
        ml1 = fmaxf(ml1, __shfl_xor_sync(0xffffffffu, ml1, 1));
        ml1 = fmaxf(ml1, __shfl_xor_sync(0xffffffffu, ml1, 2));
        const float mn0 = fmaxf(mprev0, ml0);
        const float mn1 = fmaxf(mprev1, ml1);
        const float al0 = __expf(mprev0 - mn0);
        const float al1 = __expf(mprev1 - mn1);
        float sum0 = 0.f, sum1 = 0.f;
        #pragma unroll
        for (int j = 0; j < 4; j++) {
            s[j][0] = __expf(s[j][0] - mn0); sum0 += s[j][0];
            s[j][1] = __expf(s[j][1] - mn0); sum0 += s[j][1];
            s[j][2] = __expf(s[j][2] - mn1); sum1 += s[j][2];
            s[j][3] = __expf(s[j][3] - mn1); sum1 += s[j][3];
        }
        lp0 = lp0 * al0 + sum0;
        lp1 = lp1 * al1 + sum1;
        mprev0 = mn0; mprev1 = mn1;
        #pragma unroll
        for (int j = 0; j < 8; j++) {
            o[j][0] *= al0; o[j][1] *= al0;
            o[j][2] *= al1; o[j][3] *= al1;
        }

        // ---- P -> smem (C-frag -> A-frag layout) ----
        #pragma unroll
        for (int j = 0; j < 4; j++) {
            *(uint2*)&Ps[rbase + g][j * 8 + 2 * q]     = make_uint2(f2tf(s[j][0]), f2tf(s[j][1]));
            *(uint2*)&Ps[rbase + 8 + g][j * 8 + 2 * q] = make_uint2(f2tf(s[j][2]), f2tf(s[j][3]));
        }
        __syncwarp();

        // ---- O += P V ----
        #pragma unroll
        for (int t = 0; t < 4; t++) {
            uint32_t af[4];
            af[0] = Ps[rbase + g][t * 8 + q];
            af[1] = Ps[rbase + 8 + g][t * 8 + q];
            af[2] = Ps[rbase + g][t * 8 + 4 + q];
            af[3] = Ps[rbase + 8 + g][t * 8 + 4 + q];
            #pragma unroll
            for (int j = 0; j < 8; j++) {
                uint32_t bv[2];
                bv[0] = __float_as_uint(Vs[st][t * 8 + q][j * 8 + g]);
                bv[1] = __float_as_uint(Vs[st][t * 8 + 4 + q][j * 8 + g]);
                mma8(o[j], af, bv);
            }
        }
        __syncthreads();
    }

    // ---- finalize: normalize, gate with R, round, scatter to [B,S,DX] ----
    lp0 += __shfl_xor_sync(0xffffffffu, lp0, 1);
    lp0 += __shfl_xor_sync(0xffffffffu, lp0, 2);
    lp1 += __shfl_xor_sync(0xffffffffu, lp1, 1);
    lp1 += __shfl_xor_sync(0xffffffffu, lp1, 2);
    const float inv0 = 1.0f / lp0, inv1 = 1.0f / lp1;

    const int b = bh >> 4, hh = bh & 15;
    const int s0 = q0 + rbase + g;
    const float* Rb = Rg + (size_t)bh * SEQ * HD;
    #pragma unroll
    for (int j = 0; j < 8; j++) {
        const int d = j * 8 + 2 * q;
        float2 r0v = *(const float2*)&Rb[(size_t)s0 * HD + d];
        float2 r1v = *(const float2*)&Rb[(size_t)(s0 + 8) * HD + d];
        *(float2*)&gated[(size_t)(b * SEQ + s0) * DXC + hh * HD + d] =
            make_float2(rnd_tf(o[j][0] * inv0 * r0v.x), rnd_tf(o[j][1] * inv0 * r0v.y));
        *(float2*)&gated[(size_t)(b * SEQ + s0 + 8) * DXC + hh * HD + d] =
            make_float2(rnd_tf(o[j][2] * inv1 * r1v.x), rnd_tf(o[j][3] * inv1 * r1v.y));
    }
}

// ---------------- launch ----------------
extern "C" void kernel_launch(void* const* d_in, const int* in_sizes, int n_in,
                              void* d_out, int out_size)
{
    const float* value  = (const float*)d_in[0];
    const float* key_   = (const float*)d_in[1];
    const float* query  = (const float*)d_in[2];
    const float* Wq_w   = (const float*)d_in[3];
    const float* Wq_b   = (const float*)d_in[4];
    const float* Wk_w   = (const float*)d_in[5];
    const float* Wk_b   = (const float*)d_in[6];
    const float* Wv_w   = (const float*)d_in[7];
    const float* Wv_b   = (const float*)d_in[8];
    const float* Wr_w   = (const float*)d_in[9];
    const float* Wr_b   = (const float*)d_in[10];
    const float* Wout_w = (const float*)d_in[11];
    const float* Wout_b = (const float*)d_in[12];
    float* out = (float*)d_out;

    float *pQ, *pK, *pV, *pR, *pG;
    float *pxq, *pxk, *pxv, *pwq, *pwk, *pwv, *pwr, *pwo;
    cudaGetSymbolAddress((void**)&pQ, g_Q);
    cudaGetSymbolAddress((void**)&pK, g_K);
    cudaGetSymbolAddress((void**)&pV, g_V);
    cudaGetSymbolAddress((void**)&pR, g_R);
    cudaGetSymbolAddress((void**)&pG, g_gated);
    cudaGetSymbolAddress((void**)&pxq, g_xq);
    cudaGetSymbolAddress((void**)&pxk, g_xk);
    cudaGetSymbolAddress((void**)&pxv, g_xv);
    cudaGetSymbolAddress((void**)&pwq, g_wq);
    cudaGetSymbolAddress((void**)&pwk, g_wk);
    cudaGetSymbolAddress((void**)&pwv, g_wv);
    cudaGetSymbolAddress((void**)&pwr, g_wr);
    cudaGetSymbolAddress((void**)&pwo, g_wo);

    const int nin4 = MROWS * DXC / 4;   // 2,097,152
    const int nw4  = DXC * DXC / 4;     // 262,144
    round_tf32_kernel<<<(nin4 + 255) / 256, 256>>>(query, pxq, nin4);
    round_tf32_kernel<<<(nin4 + 255) / 256, 256>>>(key_,  pxk, nin4);
    round_tf32_kernel<<<(nin4 + 255) / 256, 256>>>(value, pxv, nin4);
    round_tf32_kernel<<<(nw4 + 255) / 256, 256>>>(Wq_w, pwq, nw4);
    round_tf32_kernel<<<(nw4 + 255) / 256, 256>>>(Wk_w, pwk, nw4);
    round_tf32_kernel<<<(nw4 + 255) / 256, 256>>>(Wv_w, pwv, nw4);
    round_tf32_kernel<<<(nw4 + 255) / 256, 256>>>(Wr_w, pwr, nw4);
    round_tf32_kernel<<<(nw4 + 255) / 256, 256>>>(Wout_w, pwo, nw4);

    dim3 gGrid(DXC / 128, MROWS / 128);   // (8, 64)
    gemm_tc<<<gGrid, 256>>>(pxq, pwq, Wq_b, pQ, 1, 1);   // Q: heads, rounded
    gemm_tc<<<gGrid, 256>>>(pxk, pwk, Wk_b, pK, 1, 1);   // K: heads, rounded
    gemm_tc<<<gGrid, 256>>>(pxv, pwv, Wv_b, pV, 1, 1);   // V: heads, rounded
    gemm_tc<<<gGrid, 256>>>(pxq, pwr, Wr_b, pR, 1, 0);   // R: heads, fp32

    dim3 aGrid(SEQ / 128, BATCH * NH);    // (16, 64)
    attn_tf32<<<aGrid, 256>>>(pQ, pK, pV, pR, pG);

    gemm_tc<<<gGrid, 256>>>(pG, pwo, Wout_b, out, 0, 0); // out: flat, fp32
}

// round 4
// speedup vs baseline: 5.2753x; 1.0866x over previous
#include <cuda_runtime.h>
#include <math.h>
#include <stdint.h>

// ---------------- problem constants ----------------
constexpr int NH    = 16;
constexpr int HD    = 64;
constexpr int DXC   = 1024;
constexpr int BATCH = 4;
constexpr int SEQ   = 2048;
constexpr int MROWS = 8192;

// ---------------- scratch ----------------
__device__ float g_Q[BATCH * NH * SEQ * HD];     // tf32-rounded
__device__ float g_K[BATCH * NH * SEQ * HD];     // tf32-rounded
__device__ float g_V[BATCH * NH * SEQ * HD];     // tf32-rounded
__device__ float g_R[BATCH * NH * SEQ * HD];     // full fp32
__device__ float g_gated[MROWS * DXC];           // tf32-rounded
__device__ float g_xq[MROWS * DXC];
__device__ float g_xk[MROWS * DXC];
__device__ float g_xv[MROWS * DXC];
__device__ float g_wq[DXC * DXC];
__device__ float g_wk[DXC * DXC];
__device__ float g_wv[DXC * DXC];
__device__ float g_wr[DXC * DXC];
__device__ float g_wo[DXC * DXC];

// ---------------- helpers ----------------
__device__ __forceinline__ uint32_t f2tf(float f) {
    uint32_t u;
    asm("cvt.rna.tf32.f32 %0, %1;" : "=r"(u) : "f"(f));
    return u;
}
__device__ __forceinline__ float rnd_tf(float f) { return __uint_as_float(f2tf(f)); }

__device__ __forceinline__ void mma8(float* d, const uint32_t* a, const uint32_t* b) {
    asm volatile(
        "mma.sync.aligned.m16n8k8.row.col.f32.tf32.tf32.f32 "
        "{%0,%1,%2,%3},{%4,%5,%6,%7},{%8,%9},{%0,%1,%2,%3};\n"
        : "+f"(d[0]), "+f"(d[1]), "+f"(d[2]), "+f"(d[3])
        : "r"(a[0]), "r"(a[1]), "r"(a[2]), "r"(a[3]), "r"(b[0]), "r"(b[1]));
}

__device__ __forceinline__ void cpa16(void* sdst, const void* gsrc) {
    uint32_t s = (uint32_t)__cvta_generic_to_shared(sdst);
    asm volatile("cp.async.cg.shared.global [%0], [%1], 16;\n" :: "r"(s), "l"(gsrc));
}
__device__ __forceinline__ void cpa_commit() {
    asm volatile("cp.async.commit_group;\n" ::: "memory");
}
template <int N>
__device__ __forceinline__ void cpa_wait() {
    asm volatile("cp.async.wait_group %0;\n" :: "n"(N) : "memory");
}

// ---------------- elementwise tf32 rounding ----------------
__global__ void __launch_bounds__(256) round_tf32_kernel(
    const float* __restrict__ in, float* __restrict__ out, int n4)
{
    int i = blockIdx.x * blockDim.x + threadIdx.x;
    if (i < n4) {
        float4 v = ((const float4*)in)[i];
        v.x = rnd_tf(v.x); v.y = rnd_tf(v.y);
        v.z = rnd_tf(v.z); v.w = rnd_tf(v.w);
        ((float4*)out)[i] = v;
    }
}

// =====================================================================
// GEMM body: C = A[8192,1024] @ W[1024,1024]^T + bias
// BM=BN=128, BK=32, 256 threads, cp.async double-buffered.
// =====================================================================
__device__ __forceinline__ void gemm_body(
    const float* __restrict__ A, const float* __restrict__ W,
    const float* __restrict__ bias, float* __restrict__ C,
    int heads_layout, int round_out)
{
    __shared__ __align__(16) float As[2][128][36];
    __shared__ __align__(16) float Bs[2][128][36];

    const int tid = threadIdx.x, lane = tid & 31, wid = tid >> 5;
    const int g = lane >> 2, q = lane & 3;
    const int wm = (wid & 3) * 32, wn = (wid >> 2) * 64;
    const int m0 = blockIdx.y * 128, n0 = blockIdx.x * 128;

    const int lrow = tid >> 3;        // 0..31
    const int lcol = (tid & 7) * 4;   // 0..28

    float acc[2][8][4] = {};

    auto issue = [&](int st, int k0) {
        #pragma unroll
        for (int h = 0; h < 4; h++) {
            const int r = h * 32 + lrow;
            cpa16(&As[st][r][lcol], &A[(size_t)(m0 + r) * 1024 + k0 + lcol]);
            cpa16(&Bs[st][r][lcol], &W[(size_t)(n0 + r) * 1024 + k0 + lcol]);
        }
    };

    issue(0, 0);
    cpa_commit();

    constexpr int KT = 1024 / 32;
    for (int kt = 0; kt < KT; kt++) {
        const int st = kt & 1;
        if (kt + 1 < KT) {
            issue(st ^ 1, (kt + 1) * 32);
            cpa_commit();
            cpa_wait<1>();
        } else {
            cpa_wait<0>();
        }
        __syncthreads();

        #pragma unroll
        for (int kk = 0; kk < 32; kk += 8) {
            uint32_t af[2][4], bf[8][2];
            #pragma unroll
            for (int i = 0; i < 2; i++) {
                const int mb = wm + i * 16;
                af[i][0] = __float_as_uint(As[st][mb + g][kk + q]);
                af[i][1] = __float_as_uint(As[st][mb + 8 + g][kk + q]);
                af[i][2] = __float_as_uint(As[st][mb + g][kk + 4 + q]);
                af[i][3] = __float_as_uint(As[st][mb + 8 + g][kk + 4 + q]);
            }
            #pragma unroll
            for (int j = 0; j < 8; j++) {
                const int nb = wn + j * 8 + g;
                bf[j][0] = __float_as_uint(Bs[st][nb][kk + q]);
                bf[j][1] = __float_as_uint(Bs[st][nb][kk + 4 + q]);
            }
            #pragma unroll
            for (int i = 0; i < 2; i++)
                #pragma unroll
                for (int j = 0; j < 8; j++)
                    mma8(acc[i][j], af[i], bf[j]);
        }
        __syncthreads();
    }

    #pragma unroll
    for (int i = 0; i < 2; i++) {
        #pragma unroll
        for (int j = 0; j < 8; j++) {
            const int col = n0 + wn + j * 8 + 2 * q;
            const float b0 = bias[col], b1 = bias[col + 1];
            #pragma unroll
            for (int rh = 0; rh < 2; rh++) {
                const int row = m0 + wm + i * 16 + g + rh * 8;
                float v0 = acc[i][j][rh * 2 + 0] + b0;
                float v1 = acc[i][j][rh * 2 + 1] + b1;
                if (round_out) { v0 = rnd_tf(v0); v1 = rnd_tf(v1); }
                if (heads_layout) {
                    const int b = row >> 11, s = row & 2047;
                    const int h = col >> 6, d = col & 63;
                    *(float2*)&C[(size_t)((b * NH + h) * SEQ + s) * HD + d] = make_float2(v0, v1);
                } else {
                    *(float2*)&C[(size_t)row * 1024 + col] = make_float2(v0, v1);
                }
            }
        }
    }
}

// fused 4-projection kernel: grid.z selects {Q,K,V,R}
__global__ void __launch_bounds__(256, 2) proj4_kernel(
    const float* __restrict__ xq, const float* __restrict__ xk,
    const float* __restrict__ xv,
    const float* __restrict__ wq, const float* __restrict__ wk,
    const float* __restrict__ wv, const float* __restrict__ wr,
    const float* __restrict__ bq, const float* __restrict__ bk,
    const float* __restrict__ bv, const float* __restrict__ br,
    float* __restrict__ oq, float* __restrict__ ok,
    float* __restrict__ ov, float* __restrict__ orr)
{
    const float* A; const float* W; const float* bias; float* C; int rnd;
    switch (blockIdx.z) {
        case 0:  A = xq; W = wq; bias = bq; C = oq;  rnd = 1; break;
        case 1:  A = xk; W = wk; bias = bk; C = ok;  rnd = 1; break;
        case 2:  A = xv; W = wv; bias = bv; C = ov;  rnd = 1; break;
        default: A = xq; W = wr; bias = br; C = orr; rnd = 0; break;
    }
    gemm_body(A, W, bias, C, 1, rnd);
}

// single GEMM kernel (output projection)
__global__ void __launch_bounds__(256, 2) gemm_tc(
    const float* __restrict__ A, const float* __restrict__ W,
    const float* __restrict__ bias, float* __restrict__ C,
    int heads_layout, int round_out)
{
    gemm_body(A, W, bias, C, heads_layout, round_out);
}

// =====================================================================
// Flash attention (tf32 mma) + R-gating, cp.async double-buffered K/V
// BR=128 (8 warps x 16 rows), KC=32. Q,K,V pre-rounded to tf32.
// grid (SEQ/128, B*NH), 256 threads
// =====================================================================
#define AKC 32

__global__ void __launch_bounds__(256, 2) attn_tf32(
    const float* __restrict__ Qg, const float* __restrict__ Kg,
    const float* __restrict__ Vg, const float* __restrict__ Rg,
    float* __restrict__ gated)
{
    __shared__ __align__(16) float Ks[2][AKC][68];
    __shared__ __align__(16) float Vs[2][AKC][72];
    __shared__ __align__(16) uint32_t Ps[128][36];

    const int tid = threadIdx.x, lane = tid & 31, wid = tid >> 5;
    const int g = lane >> 2, q = lane & 3;
    const int bh = blockIdx.y;
    const int q0 = blockIdx.x * 128;
    const int rbase = wid * 16;

    const float* Qb = Qg + (size_t)bh * SEQ * HD;
    const float* Kb = Kg + (size_t)bh * SEQ * HD;
    const float* Vb = Vg + (size_t)bh * SEQ * HD;

    // Q fragments in registers (pre-rounded tf32 bits)
    uint32_t qf[8][4];
    {
        const int r0 = q0 + rbase + g;
        #pragma unroll
        for (int t = 0; t < 8; t++) {
            qf[t][0] = __float_as_uint(Qb[(size_t)r0 * HD + t * 8 + q]);
            qf[t][1] = __float_as_uint(Qb[(size_t)(r0 + 8) * HD + t * 8 + q]);
            qf[t][2] = __float_as_uint(Qb[(size_t)r0 * HD + t * 8 + 4 + q]);
            qf[t][3] = __float_as_uint(Qb[(size_t)(r0 + 8) * HD + t * 8 + 4 + q]);
        }
    }

    const int lr = tid >> 4;          // 0..15
    const int lc = (tid & 15) * 4;    // 0..60
    auto issue = [&](int st, int kb) {
        #pragma unroll
        for (int h = 0; h < 2; h++) {
            const int r = h * 16 + lr;
            cpa16(&Ks[st][r][lc], &Kb[(size_t)(kb + r) * HD + lc]);
            cpa16(&Vs[st][r][lc], &Vb[(size_t)(kb + r) * HD + lc]);
        }
    };

    float o[8][4] = {};
    float mprev0 = -1e30f, mprev1 = -1e30f;
    float lp0 = 0.f, lp1 = 0.f;

    issue(0, 0);
    cpa_commit();

    constexpr int NT = SEQ / AKC;
    for (int kt = 0; kt < NT; kt++) {
        const int st = kt & 1;
        if (kt + 1 < NT) {
            issue(st ^ 1, (kt + 1) * AKC);
            cpa_commit();
            cpa_wait<1>();
        } else {
            cpa_wait<0>();
        }
        __syncthreads();

        // ---- S = Q K^T ----
        float s[4][4] = {};
        #pragma unroll
        for (int t = 0; t < 8; t++) {
            #pragma unroll
            for (int j = 0; j < 4; j++) {
                uint32_t bf[2];
                bf[0] = __float_as_uint(Ks[st][j * 8 + g][t * 8 + q]);
                bf[1] = __float_as_uint(Ks[st][j * 8 + g][t * 8 + 4 + q]);
                mma8(s[j], qf[t], bf);
            }
        }
        #pragma unroll
        for (int j = 0; j < 4; j++)
            #pragma unroll
            for (int e = 0; e < 4; e++) s[j][e] *= 0.125f;

        // ---- online softmax ----
        float ml0 = s[0][0], ml1 = s[0][2];
        #pragma unroll
        for (int j = 0; j < 4; j++) {
            ml0 = fmaxf(ml0, fmaxf(s[j][0], s[j][1]));
            ml1 = fmaxf(ml1, fmaxf(s[j][2], s[j][3]));
        }
        ml0 = fmaxf(ml0, __shfl_xor_sync(0xffffffffu, ml0, 1));
        ml0 = fmaxf(ml0, __shfl_xor_sync(0xffffffffu, ml0, 2));
        ml1 = fmaxf(ml1, __shfl_xor_sync(0xffffffffu, ml1, 1));
        ml1 = fmaxf(ml1, __shfl_xor_sync(0xffffffffu, ml1, 2));
        const float mn0 = fmaxf(mprev0, ml0);
        const float mn1 = fmaxf(mprev1, ml1);
        const float al0 = __expf(mprev0 - mn0);
        const float al1 = __expf(mprev1 - mn1);
        float sum0 = 0.f, sum1 = 0.f;
        #pragma unroll
        for (int j = 0; j < 4; j++) {
            s[j][0] = __expf(s[j][0] - mn0); sum0 += s[j][0];
            s[j][1] = __expf(s[j][1] - mn0); sum0 += s[j][1];
            s[j][2] = __expf(s[j][2] - mn1); sum1 += s[j][2];
            s[j][3] = __expf(s[j][3] - mn1); sum1 += s[j][3];
        }
        lp0 = lp0 * al0 + sum0;
        lp1 = lp1 * al1 + sum1;
        mprev0 = mn0; mprev1 = mn1;
        #pragma unroll
        for (int j = 0; j < 8; j++) {
            o[j][0] *= al0; o[j][1] *= al0;
            o[j][2] *= al1; o[j][3] *= al1;
        }

        // ---- P -> smem (C-frag -> A-frag layout) ----
        #pragma unroll
        for (int j = 0; j < 4; j++) {
            *(uint2*)&Ps[rbase + g][j * 8 + 2 * q]     = make_uint2(f2tf(s[j][0]), f2tf(s[j][1]));
            *(uint2*)&Ps[rbase + 8 + g][j * 8 + 2 * q] = make_uint2(f2tf(s[j][2]), f2tf(s[j][3]));
        }
        __syncwarp();

        // ---- O += P V ----
        #pragma unroll
        for (int t = 0; t < 4; t++) {
            uint32_t af[4];
            af[0] = Ps[rbase + g][t * 8 + q];
            af[1] = Ps[rbase + 8 + g][t * 8 + q];
            af[2] = Ps[rbase + g][t * 8 + 4 + q];
            af[3] = Ps[rbase + 8 + g][t * 8 + 4 + q];
            #pragma unroll
            for (int j = 0; j < 8; j++) {
                uint32_t bv[2];
                bv[0] = __float_as_uint(Vs[st][t * 8 + q][j * 8 + g]);
                bv[1] = __float_as_uint(Vs[st][t * 8 + 4 + q][j * 8 + g]);
                mma8(o[j], af, bv);
            }
        }
        __syncthreads();
    }

    // ---- finalize: normalize, gate with R, round, scatter to [B,S,DX] ----
    lp0 += __shfl_xor_sync(0xffffffffu, lp0, 1);
    lp0 += __shfl_xor_sync(0xffffffffu, lp0, 2);
    lp1 += __shfl_xor_sync(0xffffffffu, lp1, 1);
    lp1 += __shfl_xor_sync(0xffffffffu, lp1, 2);
    const float inv0 = 1.0f / lp0, inv1 = 1.0f / lp1;

    const int b = bh >> 4, hh = bh & 15;
    const int s0 = q0 + rbase + g;
    const float* Rb = Rg + (size_t)bh * SEQ * HD;
    #pragma unroll
    for (int j = 0; j < 8; j++) {
        const int d = j * 8 + 2 * q;
        float2 r0v = *(const float2*)&Rb[(size_t)s0 * HD + d];
        float2 r1v = *(const float2*)&Rb[(size_t)(s0 + 8) * HD + d];
        *(float2*)&gated[(size_t)(b * SEQ + s0) * DXC + hh * HD + d] =
            make_float2(rnd_tf(o[j][0] * inv0 * r0v.x), rnd_tf(o[j][1] * inv0 * r0v.y));
        *(float2*)&gated[(size_t)(b * SEQ + s0 + 8) * DXC + hh * HD + d] =
            make_float2(rnd_tf(o[j][2] * inv1 * r1v.x), rnd_tf(o[j][3] * inv1 * r1v.y));
    }
}

// ---------------- launch ----------------
extern "C" void kernel_launch(void* const* d_in, const int* in_sizes, int n_in,
                              void* d_out, int out_size)
{
    const float* value  = (const float*)d_in[0];
    const float* key_   = (const float*)d_in[1];
    const float* query  = (const float*)d_in[2];
    const float* Wq_w   = (const float*)d_in[3];
    const float* Wq_b   = (const float*)d_in[4];
    const float* Wk_w   = (const float*)d_in[5];
    const float* Wk_b   = (const float*)d_in[6];
    const float* Wv_w   = (const float*)d_in[7];
    const float* Wv_b   = (const float*)d_in[8];
    const float* Wr_w   = (const float*)d_in[9];
    const float* Wr_b   = (const float*)d_in[10];
    const float* Wout_w = (const float*)d_in[11];
    const float* Wout_b = (const float*)d_in[12];
    float* out = (float*)d_out;

    float *pQ, *pK, *pV, *pR, *pG;
    float *pxq, *pxk, *pxv, *pwq, *pwk, *pwv, *pwr, *pwo;
    cudaGetSymbolAddress((void**)&pQ, g_Q);
    cudaGetSymbolAddress((void**)&pK, g_K);
    cudaGetSymbolAddress((void**)&pV, g_V);
    cudaGetSymbolAddress((void**)&pR, g_R);
    cudaGetSymbolAddress((void**)&pG, g_gated);
    cudaGetSymbolAddress((void**)&pxq, g_xq);
    cudaGetSymbolAddress((void**)&pxk, g_xk);
    cudaGetSymbolAddress((void**)&pxv, g_xv);
    cudaGetSymbolAddress((void**)&pwq, g_wq);
    cudaGetSymbolAddress((void**)&pwk, g_wk);
    cudaGetSymbolAddress((void**)&pwv, g_wv);
    cudaGetSymbolAddress((void**)&pwr, g_wr);
    cudaGetSymbolAddress((void**)&pwo, g_wo);

    const int nin4 = MROWS * DXC / 4;
    const int nw4  = DXC * DXC / 4;
    round_tf32_kernel<<<(nin4 + 255) / 256, 256>>>(query, pxq, nin4);
    round_tf32_kernel<<<(nin4 + 255) / 256, 256>>>(key_,  pxk, nin4);
    round_tf32_kernel<<<(nin4 + 255) / 256, 256>>>(value, pxv, nin4);
    round_tf32_kernel<<<(nw4 + 255) / 256, 256>>>(Wq_w, pwq, nw4);
    round_tf32_kernel<<<(nw4 + 255) / 256, 256>>>(Wk_w, pwk, nw4);
    round_tf32_kernel<<<(nw4 + 255) / 256, 256>>>(Wv_w, pwv, nw4);
    round_tf32_kernel<<<(nw4 + 255) / 256, 256>>>(Wr_w, pwr, nw4);
    round_tf32_kernel<<<(nw4 + 255) / 256, 256>>>(Wout_w, pwo, nw4);

    dim3 pGrid(DXC / 128, MROWS / 128, 4);   // (8, 64, 4) = 2048 blocks
    proj4_kernel<<<pGrid, 256>>>(pxq, pxk, pxv,
                                 pwq, pwk, pwv, pwr,
                                 Wq_b, Wk_b, Wv_b, Wr_b,
                                 pQ, pK, pV, pR);

    dim3 aGrid(SEQ / 128, BATCH * NH);       // (16, 64)
    attn_tf32<<<aGrid, 256>>>(pQ, pK, pV, pR, pG);

    dim3 gGrid(DXC / 128, MROWS / 128);      // (8, 64)
    gemm_tc<<<gGrid, 256>>>(pG, pwo, Wout_b, out, 0, 0);
}

// round 6
// speedup vs baseline: 8.5108x; 1.6133x over previous
#include <cuda_runtime.h>
#include <cuda_fp16.h>
#include <stdint.h>

// ---------------- problem constants ----------------
constexpr int NH    = 16;
constexpr int HD    = 64;
constexpr int DXC   = 1024;
constexpr int BATCH = 4;
constexpr int SEQ   = 2048;
constexpr int MROWS = 8192;

// ---------------- scratch ----------------
__device__ __half g_Qh[BATCH * NH * SEQ * HD];
__device__ __half g_Kh[BATCH * NH * SEQ * HD];
__device__ __half g_Vh[BATCH * NH * SEQ * HD];
__device__ float  g_R [BATCH * NH * SEQ * HD];
__device__ __half g_gh[MROWS * DXC];
__device__ __half g_xq[MROWS * DXC];
__device__ __half g_xk[MROWS * DXC];
__device__ __half g_xv[MROWS * DXC];
__device__ __half g_wq[DXC * DXC];
__device__ __half g_wk[DXC * DXC];
__device__ __half g_wv[DXC * DXC];
__device__ __half g_wr[DXC * DXC];
__device__ __half g_wo[DXC * DXC];

// ---------------- helpers ----------------
__device__ __forceinline__ void mma16(float* d, const uint32_t* a, const uint32_t* b) {
    asm volatile(
        "mma.sync.aligned.m16n8k16.row.col.f32.f16.f16.f32 "
        "{%0,%1,%2,%3},{%4,%5,%6,%7},{%8,%9},{%0,%1,%2,%3};\n"
        : "+f"(d[0]), "+f"(d[1]), "+f"(d[2]), "+f"(d[3])
        : "r"(a[0]), "r"(a[1]), "r"(a[2]), "r"(a[3]), "r"(b[0]), "r"(b[1]));
}

__device__ __forceinline__ uint32_t smem_u32(const void* p) {
    return (uint32_t)__cvta_generic_to_shared(p);
}
__device__ __forceinline__ void cpa16(void* sdst, const void* gsrc) {
    uint32_t s = smem_u32(sdst);
    asm volatile("cp.async.cg.shared.global [%0], [%1], 16;\n" :: "r"(s), "l"(gsrc));
}
__device__ __forceinline__ void cpa_commit() {
    asm volatile("cp.async.commit_group;\n" ::: "memory");
}
template <int N>
__device__ __forceinline__ void cpa_wait() {
    asm volatile("cp.async.wait_group %0;\n" :: "n"(N) : "memory");
}
__device__ __forceinline__ void ldsm_x4_t(uint32_t* r, uint32_t addr) {
    asm volatile("ldmatrix.sync.aligned.m8n8.x4.trans.shared.b16 {%0,%1,%2,%3}, [%4];"
        : "=r"(r[0]), "=r"(r[1]), "=r"(r[2]), "=r"(r[3]) : "r"(addr));
}

// ---------------- fp32 -> fp16 convert ----------------
__global__ void __launch_bounds__(256) tohalf_kernel(
    const float* __restrict__ in, __half* __restrict__ out, int n4)
{
    int i = blockIdx.x * blockDim.x + threadIdx.x;
    if (i < n4) {
        float4 v = ((const float4*)in)[i];
        ((__half2*)out)[i * 2 + 0] = __floats2half2_rn(v.x, v.y);
        ((__half2*)out)[i * 2 + 1] = __floats2half2_rn(v.z, v.w);
    }
}

// =====================================================================
// fp16 GEMM: C = A[8192,1024] @ W[1024,1024]^T + bias
// BM=BN=128, BK=32 (half), 256 threads, 2-stage cp.async.
// mode: 0 = half heads-layout, 1 = float heads-layout, 2 = float flat
// =====================================================================
__device__ __forceinline__ void gemm16_body(
    const __half* __restrict__ A, const __half* __restrict__ W,
    const float* __restrict__ bias, void* __restrict__ Cv, int mode)
{
    __shared__ __align__(16) __half As[2][128][40];
    __shared__ __align__(16) __half Bs[2][128][40];

    const int tid = threadIdx.x, lane = tid & 31, wid = tid >> 5;
    const int g = lane >> 2, q = lane & 3;
    const int wm = (wid & 3) * 32, wn = (wid >> 2) * 64;
    const int m0 = blockIdx.y * 128, n0 = blockIdx.x * 128;

    float acc[2][8][4] = {};

    auto issue = [&](int st, int k0) {
        #pragma unroll
        for (int c = 0; c < 2; c++) {
            const int id = c * 256 + tid;
            const int r = id >> 2, sg = (id & 3) * 8;
            cpa16(&As[st][r][sg], &A[(size_t)(m0 + r) * 1024 + k0 + sg]);
            cpa16(&Bs[st][r][sg], &W[(size_t)(n0 + r) * 1024 + k0 + sg]);
        }
    };

    issue(0, 0);
    cpa_commit();

    constexpr int KT = 1024 / 32;
    for (int kt = 0; kt < KT; kt++) {
        const int st = kt & 1;
        if (kt + 1 < KT) {
            issue(st ^ 1, (kt + 1) * 32);
            cpa_commit();
            cpa_wait<1>();
        } else {
            cpa_wait<0>();
        }
        __syncthreads();

        #pragma unroll
        for (int kk = 0; kk < 32; kk += 16) {
            uint32_t af[2][4], bf[8][2];
            #pragma unroll
            for (int i = 0; i < 2; i++) {
                const int mb = wm + i * 16;
                af[i][0] = *(const uint32_t*)&As[st][mb + g][kk + 2 * q];
                af[i][1] = *(const uint32_t*)&As[st][mb + 8 + g][kk + 2 * q];
                af[i][2] = *(const uint32_t*)&As[st][mb + g][kk + 8 + 2 * q];
                af[i][3] = *(const uint32_t*)&As[st][mb + 8 + g][kk + 8 + 2 * q];
            }
            #pragma unroll
            for (int j = 0; j < 8; j++) {
                const int nb = wn + j * 8 + g;
                bf[j][0] = *(const uint32_t*)&Bs[st][nb][kk + 2 * q];
                bf[j][1] = *(const uint32_t*)&Bs[st][nb][kk + 8 + 2 * q];
            }
            #pragma unroll
            for (int i = 0; i < 2; i++)
                #pragma unroll
                for (int j = 0; j < 8; j++)
                    mma16(acc[i][j], af[i], bf[j]);
        }
        __syncthreads();
    }

    #pragma unroll
    for (int i = 0; i < 2; i++) {
        #pragma unroll
        for (int j = 0; j < 8; j++) {
            const int col = n0 + wn + j * 8 + 2 * q;
            const float b0 = bias[col], b1 = bias[col + 1];
            #pragma unroll
            for (int rh = 0; rh < 2; rh++) {
                const int row = m0 + wm + i * 16 + g + rh * 8;
                float v0 = acc[i][j][rh * 2 + 0] + b0;
                float v1 = acc[i][j][rh * 2 + 1] + b1;
                const int b = row >> 11, s = row & 2047;
                const int h = col >> 6, d = col & 63;
                if (mode == 0) {
                    __half* C = (__half*)Cv;
                    *(__half2*)&C[(size_t)((b * NH + h) * SEQ + s) * HD + d] =
                        __floats2half2_rn(v0, v1);
                } else if (mode == 1) {
                    float* C = (float*)Cv;
                    *(float2*)&C[(size_t)((b * NH + h) * SEQ + s) * HD + d] =
                        make_float2(v0, v1);
                } else {
                    float* C = (float*)Cv;
                    *(float2*)&C[(size_t)row * 1024 + col] = make_float2(v0, v1);
                }
            }
        }
    }
}

// fused 4-projection kernel: grid.z selects {Q,K,V,R}
__global__ void __launch_bounds__(256, 2) proj4_16(
    const __half* xq, const __half* xk, const __half* xv,
    const __half* wq, const __half* wk, const __half* wv, const __half* wr,
    const float* bq, const float* bk, const float* bv, const float* br,
    __half* oq, __half* ok, __half* ov, float* orr)
{
    const __half* A; const __half* W; const float* bias; void* C; int mode;
    switch (blockIdx.z) {
        case 0:  A = xq; W = wq; bias = bq; C = oq;  mode = 0; break;
        case 1:  A = xk; W = wk; bias = bk; C = ok;  mode = 0; break;
        case 2:  A = xv; W = wv; bias = bv; C = ov;  mode = 0; break;
        default: A = xq; W = wr; bias = br; C = orr; mode = 1; break;
    }
    gemm16_body(A, W, bias, C, mode);
}

__global__ void __launch_bounds__(256, 2) gemm16_out(
    const __half* A, const __half* W, const float* bias, float* C)
{
    gemm16_body(A, W, bias, C, 2);
}

// =====================================================================
// Flash attention (fp16 mma) + R-gating
// BR=128 (8 warps x 16 rows), KC=32, cp.async double-buffered K/V.
// grid (SEQ/128, B*NH), 256 threads
// =====================================================================
#define AKC 32

__global__ void __launch_bounds__(256, 2) attn16(
    const __half* __restrict__ Qg, const __half* __restrict__ Kg,
    const __half* __restrict__ Vg, const float* __restrict__ Rg,
    __half* __restrict__ gated)
{
    __shared__ __align__(16) __half Ks[2][AKC][72];
    __shared__ __align__(16) __half Vs[2][AKC][72];
    __shared__ __align__(16) __half Ps[128][40];

    const int tid = threadIdx.x, lane = tid & 31, wid = tid >> 5;
    const int g = lane >> 2, q = lane & 3;
    const int bh = blockIdx.y;
    const int q0 = blockIdx.x * 128;
    const int rbase = wid * 16;

    const __half* Qb = Qg + (size_t)bh * SEQ * HD;
    const __half* Kb = Kg + (size_t)bh * SEQ * HD;
    const __half* Vb = Vg + (size_t)bh * SEQ * HD;

    // Q fragments in registers: 4 k-steps of 16
    uint32_t qf[4][4];
    {
        const int r0 = q0 + rbase + g;
        #pragma unroll
        for (int t = 0; t < 4; t++) {
            qf[t][0] = *(const uint32_t*)&Qb[(size_t)r0 * HD + 16 * t + 2 * q];
            qf[t][1] = *(const uint32_t*)&Qb[(size_t)(r0 + 8) * HD + 16 * t + 2 * q];
            qf[t][2] = *(const uint32_t*)&Qb[(size_t)r0 * HD + 16 * t + 8 + 2 * q];
            qf[t][3] = *(const uint32_t*)&Qb[(size_t)(r0 + 8) * HD + 16 * t + 8 + 2 * q];
        }
    }

    // K/V tile loads: 32 rows x 64 halves (128B) -> 8 cpa16/row
    auto issue = [&](int st, int kb) {
        const int r = tid >> 3, sg = (tid & 7) * 8;
        cpa16(&Ks[st][r][sg], &Kb[(size_t)(kb + r) * HD + sg]);
        cpa16(&Vs[st][r][sg], &Vb[(size_t)(kb + r) * HD + sg]);
    };

    float o[8][4] = {};
    float mprev0 = -1e30f, mprev1 = -1e30f;
    float lp0 = 0.f, lp1 = 0.f;

    issue(0, 0);
    cpa_commit();

    constexpr int NT = SEQ / AKC;
    for (int kt = 0; kt < NT; kt++) {
        const int st = kt & 1;
        if (kt + 1 < NT) {
            issue(st ^ 1, (kt + 1) * AKC);
            cpa_commit();
            cpa_wait<1>();
        } else {
            cpa_wait<0>();
        }
        __syncthreads();

        // ---- S = Q K^T ----
        float s[4][4] = {};
        #pragma unroll
        for (int t = 0; t < 4; t++) {
            #pragma unroll
            for (int j = 0; j < 4; j++) {
                uint32_t bf[2];
                const int nb = j * 8 + g;
                bf[0] = *(const uint32_t*)&Ks[st][nb][16 * t + 2 * q];
                bf[1] = *(const uint32_t*)&Ks[st][nb][16 * t + 8 + 2 * q];
                mma16(s[j], qf[t], bf);
            }
        }
        #pragma unroll
        for (int j = 0; j < 4; j++)
            #pragma unroll
            for (int e = 0; e < 4; e++) s[j][e] *= 0.125f;

        // ---- online softmax ----
        float ml0 = s[0][0], ml1 = s[0][2];
        #pragma unroll
        for (int j = 0; j < 4; j++) {
            ml0 = fmaxf(ml0, fmaxf(s[j][0], s[j][1]));
            ml1 = fmaxf(ml1, fmaxf(s[j][2], s[j][3]));
        }
        ml0 = fmaxf(ml0, __shfl_xor_sync(0xffffffffu, ml0, 1));
        ml0 = fmaxf(ml0, __shfl_xor_sync(0xffffffffu, ml0, 2));
        ml1 = fmaxf(ml1, __shfl_xor_sync(0xffffffffu, ml1, 1));
        ml1 = fmaxf(ml1, __shfl_xor_sync(0xffffffffu, ml1, 2));
        const float mn0 = fmaxf(mprev0, ml0);
        const float mn1 = fmaxf(mprev1, ml1);
        const float al0 = __expf(mprev0 - mn0);
        const float al1 = __expf(mprev1 - mn1);
        float sum0 = 0.f, sum1 = 0.f;
        #pragma unroll
        for (int j = 0; j < 4; j++) {
            s[j][0] = __expf(s[j][0] - mn0); sum0 += s[j][0];
            s[j][1] = __expf(s[j][1] - mn0); sum0 += s[j][1];
            s[j][2] = __expf(s[j][2] - mn1); sum1 += s[j][2];
            s[j][3] = __expf(s[j][3] - mn1); sum1 += s[j][3];
        }
        lp0 = lp0 * al0 + sum0;
        lp1 = lp1 * al1 + sum1;
        mprev0 = mn0; mprev1 = mn1;
        #pragma unroll
        for (int j = 0; j < 8; j++) {
            o[j][0] *= al0; o[j][1] *= al0;
            o[j][2] *= al1; o[j][3] *= al1;
        }

        // ---- P -> smem (half) ----
        #pragma unroll
        for (int j = 0; j < 4; j++) {
            *(__half2*)&Ps[rbase + g][j * 8 + 2 * q]     = __floats2half2_rn(s[j][0], s[j][1]);
            *(__half2*)&Ps[rbase + 8 + g][j * 8 + 2 * q] = __floats2half2_rn(s[j][2], s[j][3]);
        }
        __syncwarp();

        // ---- O += P V ----
        #pragma unroll
        for (int kk = 0; kk < AKC; kk += 16) {
            uint32_t af[4];
            af[0] = *(const uint32_t*)&Ps[rbase + g][kk + 2 * q];
            af[1] = *(const uint32_t*)&Ps[rbase + 8 + g][kk + 2 * q];
            af[2] = *(const uint32_t*)&Ps[rbase + g][kk + 8 + 2 * q];
            af[3] = *(const uint32_t*)&Ps[rbase + 8 + g][kk + 8 + 2 * q];
            #pragma unroll
            for (int jj = 0; jj < 4; jj++) {
                uint32_t bv[4];
                const uint32_t addr = smem_u32(
                    &Vs[st][kk + (lane & 15)][jj * 16 + ((lane >> 4) << 3)]);
                ldsm_x4_t(bv, addr);
                mma16(o[2 * jj + 0], af, bv);
                mma16(o[2 * jj + 1], af, bv + 2);
            }
        }
        __syncthreads();
    }

    // ---- finalize: normalize, gate with R, write half gated ----
    lp0 += __shfl_xor_sync(0xffffffffu, lp0, 1);
    lp0 += __shfl_xor_sync(0xffffffffu, lp0, 2);
    lp1 += __shfl_xor_sync(0xffffffffu, lp1, 1);
    lp1 += __shfl_xor_sync(0xffffffffu, lp1, 2);
    const float inv0 = 1.0f / lp0, inv1 = 1.0f / lp1;

    const int b = bh >> 4, hh = bh & 15;
    const int s0 = q0 + rbase + g;
    const float* Rb = Rg + (size_t)bh * SEQ * HD;
    #pragma unroll
    for (int j = 0; j < 8; j++) {
        const int d = j * 8 + 2 * q;
        float2 r0v = *(const float2*)&Rb[(size_t)s0 * HD + d];
        float2 r1v = *(const float2*)&Rb[(size_t)(s0 + 8) * HD + d];
        *(__half2*)&gated[(size_t)(b * SEQ + s0) * DXC + hh * HD + d] =
            __floats2half2_rn(o[j][0] * inv0 * r0v.x, o[j][1] * inv0 * r0v.y);
        *(__half2*)&gated[(size_t)(b * SEQ + s0 + 8) * DXC + hh * HD + d] =
            __floats2half2_rn(o[j][2] * inv1 * r1v.x, o[j][3] * inv1 * r1v.y);
    }
}

// ---------------- launch ----------------
extern "C" void kernel_launch(void* const* d_in, const int* in_sizes, int n_in,
                              void* d_out, int out_size)
{
    const float* value  = (const float*)d_in[0];
    const float* key_   = (const float*)d_in[1];
    const float* query  = (const float*)d_in[2];
    const float* Wq_w   = (const float*)d_in[3];
    const float* Wq_b   = (const float*)d_in[4];
    const float* Wk_w   = (const float*)d_in[5];
    const float* Wk_b   = (const float*)d_in[6];
    const float* Wv_w   = (const float*)d_in[7];
    const float* Wv_b   = (const float*)d_in[8];
    const float* Wr_w   = (const float*)d_in[9];
    const float* Wr_b   = (const float*)d_in[10];
    const float* Wout_w = (const float*)d_in[11];
    const float* Wout_b = (const float*)d_in[12];
    float* out = (float*)d_out;

    __half *pQ, *pK, *pV, *pG, *pxq, *pxk, *pxv, *pwq, *pwk, *pwv, *pwr, *pwo;
    float *pR;
    cudaGetSymbolAddress((void**)&pQ, g_Qh);
    cudaGetSymbolAddress((void**)&pK, g_Kh);
    cudaGetSymbolAddress((void**)&pV, g_Vh);
    cudaGetSymbolAddress((void**)&pR, g_R);
    cudaGetSymbolAddress((void**)&pG, g_gh);
    cudaGetSymbolAddress((void**)&pxq, g_xq);
    cudaGetSymbolAddress((void**)&pxk, g_xk);
    cudaGetSymbolAddress((void**)&pxv, g_xv);
    cudaGetSymbolAddress((void**)&pwq, g_wq);
    cudaGetSymbolAddress((void**)&pwk, g_wk);
    cudaGetSymbolAddress((void**)&pwv, g_wv);
    cudaGetSymbolAddress((void**)&pwr, g_wr);
    cudaGetSymbolAddress((void**)&pwo, g_wo);

    const int nin4 = MROWS * DXC / 4;
    const int nw4  = DXC * DXC / 4;
    tohalf_kernel<<<(nin4 + 255) / 256, 256>>>(query, pxq, nin4);
    tohalf_kernel<<<(nin4 + 255) / 256, 256>>>(key_,  pxk, nin4);
    tohalf_kernel<<<(nin4 + 255) / 256, 256>>>(value, pxv, nin4);
    tohalf_kernel<<<(nw4 + 255) / 256, 256>>>(Wq_w,   pwq, nw4);
    tohalf_kernel<<<(nw4 + 255) / 256, 256>>>(Wk_w,   pwk, nw4);
    tohalf_kernel<<<(nw4 + 255) / 256, 256>>>(Wv_w,   pwv, nw4);
    tohalf_kernel<<<(nw4 + 255) / 256, 256>>>(Wr_w,   pwr, nw4);
    tohalf_kernel<<<(nw4 + 255) / 256, 256>>>(Wout_w, pwo, nw4);

    dim3 pGrid(DXC / 128, MROWS / 128, 4);   // (8, 64, 4)
    proj4_16<<<pGrid, 256>>>(pxq, pxk, pxv,
                             pwq, pwk, pwv, pwr,
                             Wq_b, Wk_b, Wv_b, Wr_b,
                             pQ, pK, pV, pR);

    dim3 aGrid(SEQ / 128, BATCH * NH);       // (16, 64)
    attn16<<<aGrid, 256>>>(pQ, pK, pV, pR, pG);

    dim3 gGrid(DXC / 128, MROWS / 128);      // (8, 64)
    gemm16_out<<<gGrid, 256>>>(pG, pwo, Wout_b, out);
}